// round 16
// baseline (speedup 1.0000x reference)
#include <cuda_runtime.h>
#include <mma.h>
#include <cuda_fp16.h>
#include <cstdint>

using namespace nvcuda;

#define B_  4
#define S_  2048
#define D_  1024
#define H_  16
#define DK_ 64

// Scratch (__device__ globals; no allocs allowed).
__device__ __half g_Xq[(size_t)B_*S_*D_];
__device__ __half g_Xk[(size_t)B_*S_*D_];
__device__ __half g_Xv[(size_t)B_*S_*D_];
__device__ __half g_Wh[4][(size_t)D_*D_];
__device__ __half g_Qh[(size_t)B_*S_*D_];   // Qproj * 0.125
__device__ __half g_Kh[(size_t)B_*S_*D_];
__device__ __half g_Vh[(size_t)B_*S_*D_];
__device__ __half g_AOh[(size_t)B_*S_*D_];

__device__ __forceinline__ void cpasync16(uint32_t saddr, const void* g) {
    asm volatile("cp.async.cg.shared.global [%0], [%1], 16;" :: "r"(saddr), "l"(g));
}
__device__ __forceinline__ void cpasync_commit() {
    asm volatile("cp.async.commit_group;");
}
__device__ __forceinline__ void cpasync_wait0() {
    asm volatile("cp.async.wait_group 0;");
}

// ---------------------------------------------------------------------------
// fp32 -> fp16 conversion, all 7 tensors in one launch.
// ---------------------------------------------------------------------------
__global__ __launch_bounds__(256) void tohalf_all(
    const float* __restrict__ q,  const float* __restrict__ k,
    const float* __restrict__ v,
    const float* __restrict__ wq, const float* __restrict__ wk,
    const float* __restrict__ wv, const float* __restrict__ wo,
    __half* __restrict__ xq, __half* __restrict__ xk, __half* __restrict__ xv,
    __half* __restrict__ wh)
{
    const int z = blockIdx.y;
    const float* in; __half* o; int n4;
    const int NB = (int)((size_t)B_ * S_ * D_ / 4);
    const int NW = D_ * D_ / 4;
    if (z == 0)      { in = q;  o = xq; n4 = NB; }
    else if (z == 1) { in = k;  o = xk; n4 = NB; }
    else if (z == 2) { in = v;  o = xv; n4 = NB; }
    else if (z == 3) { in = wq; o = wh + 0 * (size_t)D_ * D_; n4 = NW; }
    else if (z == 4) { in = wk; o = wh + 1 * (size_t)D_ * D_; n4 = NW; }
    else if (z == 5) { in = wv; o = wh + 2 * (size_t)D_ * D_; n4 = NW; }
    else             { in = wo; o = wh + 3 * (size_t)D_ * D_; n4 = NW; }

    int i = blockIdx.x * 256 + threadIdx.x;
    int stride = gridDim.x * 256;
    for (; i < n4; i += stride) {
        float4 vv = ((const float4*)in)[i];
        half2 h0 = __floats2half2_rn(vv.x, vv.y);
        half2 h1 = __floats2half2_rn(vv.z, vv.w);
        uint2 pk; pk.x = *(uint32_t*)&h0; pk.y = *(uint32_t*)&h1;
        ((uint2*)o)[i] = pk;
    }
}

// ---------------------------------------------------------------------------
// fp16 NT GEMM, BM=64 / BN=128 / BK=64, 3 CTAs/SM.
// 8 warps (2 x 4), warp tile 32x32. cp.async double-buffered.
// mode 0: fp32 out. 1: half out. 2: half out * 0.125.
// ---------------------------------------------------------------------------
#define GA_BUF 9216
#define GB_BUF 18432
#define GB_BASE 18432
#define GCS_BASE 55296
#define G16_SMEM_BYTES 65536

__device__ __forceinline__ void gemm16_body(
    const __half* __restrict__ A, const __half* __restrict__ W,
    const float* __restrict__ bias, float* __restrict__ Cf,
    __half* __restrict__ Ch, int mode, char* smc)
{
    const int tid = threadIdx.x;
    const int w = tid >> 5, lane = tid & 31;
    const int wm = w >> 2, wn = w & 3;
    const size_t m0 = (size_t)blockIdx.y * 64;
    const size_t n0 = (size_t)blockIdx.x * 128;
    const uint32_t smb = (uint32_t)__cvta_generic_to_shared(smc);
    const int crow = tid >> 3, cc = tid & 7;

    wmma::fragment<wmma::accumulator, 16, 16, 16, float> c[2][2];
#pragma unroll
    for (int i = 0; i < 2; i++)
#pragma unroll
        for (int j = 0; j < 2; j++) wmma::fill_fragment(c[i][j], 0.f);

#pragma unroll
    for (int it = 0; it < 2; it++) {
        int row = crow + 32 * it;
        cpasync16(smb + row * 144 + cc * 16,
                  A + (m0 + row) * 1024 + cc * 8);
    }
#pragma unroll
    for (int it = 0; it < 4; it++) {
        int row = crow + 32 * it;
        cpasync16(smb + GB_BASE + row * 144 + cc * 16,
                  W + (n0 + row) * 1024 + cc * 8);
    }
    cpasync_commit();

    for (int kb = 0; kb < 16; kb++) {
        const int cur = kb & 1;
        cpasync_wait0();
        __syncthreads();

        if (kb < 15) {
            const int nxt = 1 - cur;
            const int k0 = (kb + 1) * 64;
#pragma unroll
            for (int it = 0; it < 2; it++) {
                int row = crow + 32 * it;
                cpasync16(smb + nxt * GA_BUF + row * 144 + cc * 16,
                          A + (m0 + row) * 1024 + k0 + cc * 8);
            }
#pragma unroll
            for (int it = 0; it < 4; it++) {
                int row = crow + 32 * it;
                cpasync16(smb + GB_BASE + nxt * GB_BUF + row * 144 + cc * 16,
                          W + (n0 + row) * 1024 + k0 + cc * 8);
            }
            cpasync_commit();
        }

        const __half* ah = (const __half*)(smc + cur * GA_BUF);
        const __half* bh = (const __half*)(smc + GB_BASE + cur * GB_BUF);
#pragma unroll
        for (int ks = 0; ks < 4; ks++) {
            wmma::fragment<wmma::matrix_a, 16, 16, 16, __half, wmma::row_major> a[2];
            wmma::fragment<wmma::matrix_b, 16, 16, 16, __half, wmma::col_major> b[2];
#pragma unroll
            for (int i = 0; i < 2; i++)
                wmma::load_matrix_sync(a[i], &ah[(32 * wm + 16 * i) * 72 + ks * 16], 72);
#pragma unroll
            for (int j = 0; j < 2; j++)
                wmma::load_matrix_sync(b[j], &bh[(32 * wn + 16 * j) * 72 + ks * 16], 72);
#pragma unroll
            for (int i = 0; i < 2; i++)
#pragma unroll
                for (int j = 0; j < 2; j++)
                    wmma::mma_sync(c[i][j], a[i], b[j], c[i][j]);
        }
    }

    float* buf = (float*)(smc + GCS_BASE) + w * 320;
#pragma unroll
    for (int i = 0; i < 2; i++) {
#pragma unroll
        for (int j = 0; j < 2; j++) {
            wmma::store_matrix_sync(buf, c[i][j], 20, wmma::mem_row_major);
            __syncwarp();
            const int rr = lane >> 1, ch = (lane & 1) * 8;
            const size_t gr = m0 + 32 * wm + 16 * i + rr;
            const size_t gc = n0 + 32 * wn + 16 * j + ch;
            float4 v0 = *(float4*)&buf[rr * 20 + ch];
            float4 v1 = *(float4*)&buf[rr * 20 + ch + 4];
            v0.x += bias[gc + 0]; v0.y += bias[gc + 1];
            v0.z += bias[gc + 2]; v0.w += bias[gc + 3];
            v1.x += bias[gc + 4]; v1.y += bias[gc + 5];
            v1.z += bias[gc + 6]; v1.w += bias[gc + 7];
            if (mode == 0) {
                *(float4*)(Cf + gr * 1024 + gc)     = v0;
                *(float4*)(Cf + gr * 1024 + gc + 4) = v1;
            } else {
                if (mode == 2) {
                    v0.x *= 0.125f; v0.y *= 0.125f; v0.z *= 0.125f; v0.w *= 0.125f;
                    v1.x *= 0.125f; v1.y *= 0.125f; v1.z *= 0.125f; v1.w *= 0.125f;
                }
                half2 h0 = __floats2half2_rn(v0.x, v0.y);
                half2 h1 = __floats2half2_rn(v0.z, v0.w);
                half2 h2 = __floats2half2_rn(v1.x, v1.y);
                half2 h3 = __floats2half2_rn(v1.z, v1.w);
                uint4 pk;
                pk.x = *(uint32_t*)&h0; pk.y = *(uint32_t*)&h1;
                pk.z = *(uint32_t*)&h2; pk.w = *(uint32_t*)&h3;
                *(uint4*)(Ch + gr * 1024 + gc) = pk;
            }
            __syncwarp();
        }
    }
}

__global__ __launch_bounds__(256, 3) void qkv16(
    const __half* __restrict__ xq, const __half* __restrict__ xk,
    const __half* __restrict__ xv,
    const __half* __restrict__ wq, const float* __restrict__ bq,
    const __half* __restrict__ wk, const float* __restrict__ bk,
    const __half* __restrict__ wv, const float* __restrict__ bv,
    __half* __restrict__ Qo, __half* __restrict__ Ko, __half* __restrict__ Vo)
{
    extern __shared__ char smc[];
    const __half *A, *W; const float* bi; __half* C; int mode;
    if (blockIdx.z == 0)      { A = xq; W = wq; bi = bq; C = Qo; mode = 2; }
    else if (blockIdx.z == 1) { A = xk; W = wk; bi = bk; C = Ko; mode = 1; }
    else                      { A = xv; W = wv; bi = bv; C = Vo; mode = 1; }
    gemm16_body(A, W, bi, nullptr, C, mode, smc);
}

__global__ __launch_bounds__(256, 3) void out16(
    const __half* __restrict__ A, const __half* __restrict__ W,
    const float* __restrict__ bi, float* __restrict__ C)
{
    extern __shared__ char smc[];
    gemm16_body(A, W, bi, C, nullptr, 0, smc);
}

// ---------------------------------------------------------------------------
// Fused attention, TWO-PASS.
// Pass 1: rowsums in fragments, k-chunk=128 (16 iters, 1 barrier each),
//   K double-buffered in the KB+VB region (2 x 128 x 144B).
// Pass 2: k-chunk=64; per-warp own-region staging builds PsH (normalized
//   half), PV MMA, THEN fp32 P write from Sst (overlaps tensor drain).
// Smem: Sst f32 128*72 @0, PsH half @36864, KB dbl @55296, VB dbl @73728.
// ---------------------------------------------------------------------------
#define FA_SMEM_BYTES 92160
#define KB_BOFF 55296
#define VB_BOFF 73728
#define KV_BSTRIDE 9216
#define P1K_BUF 18432   // pass-1 K buffer stride (128 rows x 144B)

__global__ __launch_bounds__(256, 2) void fused_attn16(
    const __half* __restrict__ Q, const __half* __restrict__ K,
    const __half* __restrict__ V, float* __restrict__ P,
    __half* __restrict__ AO)
{
    extern __shared__ char smc[];
    float*  Sst = (float*)smc;
    __half* PsH = (__half*)(smc + 36864);
    const uint32_t smb = (uint32_t)__cvta_generic_to_shared(smc);

    const int tid = threadIdx.x, w = tid >> 5, lane = tid & 31;
    const int wm = w >> 1, wn = w & 1;          // 4x2 warp grid, 32x32 tiles
    const int bh = blockIdx.y, b = bh >> 4, h = bh & 15;
    const int q0 = blockIdx.x * 128;
    const int prow = tid >> 4, pc4 = tid & 15;  // block-wide pass mapping
    const int crow = tid >> 3, cc = tid & 7;    // copy mapping
    const int frow = lane >> 2;                 // fragment row base
    const int srow = lane >> 3, sc4 = lane & 7; // own-region staging mapping

    const __half* Qb = Q + (size_t)b * S_ * D_ + h * DK_;
    const __half* Kb = K + (size_t)b * S_ * D_ + h * DK_;
    const __half* Vb = V + (size_t)b * S_ * D_ + h * DK_;
    float* Pb = P + (size_t)bh * S_ * S_;

    // ---- Stage Q tile into PsH, preload fragments ----
#pragma unroll
    for (int it = 0; it < 4; it++) {
        int idx = tid + 256 * it;
        int row = idx >> 3, c = idx & 7;
        *(uint4*)&PsH[row * 72 + c * 8] =
            *(const uint4*)(Qb + (size_t)(q0 + row) * D_ + c * 8);
    }
    __syncthreads();
    wmma::fragment<wmma::matrix_a, 16, 16, 16, __half, wmma::row_major> Qf[4][2];
#pragma unroll
    for (int ks = 0; ks < 4; ks++)
#pragma unroll
        for (int i = 0; i < 2; i++)
            wmma::load_matrix_sync(Qf[ks][i], &PsH[(32 * wm + 16 * i) * 72 + ks * 16], 72);
    __syncthreads();

    float rs0[2] = {0.f, 0.f};
    float rs1[2] = {0.f, 0.f};

    // ================= PASS 1: rowsums, k-chunk 128 =================
#pragma unroll
    for (int it = 0; it < 4; it++) {
        int row = crow + 32 * it;
        cpasync16(smb + KB_BOFF + row * 144 + cc * 16,
                  Kb + (size_t)row * D_ + cc * 8);
    }
    cpasync_commit();

    for (int kc = 0; kc < 16; kc++) {
        const int cur = kc & 1;
        __half* Kc = (__half*)(smc + KB_BOFF + cur * P1K_BUF);

        cpasync_wait0();
        __syncthreads();

        if (kc + 1 < 16) {
            const int nxt = 1 - cur;
#pragma unroll
            for (int it = 0; it < 4; it++) {
                int row = crow + 32 * it;
                cpasync16(smb + KB_BOFF + nxt * P1K_BUF + row * 144 + cc * 16,
                          Kb + (size_t)((kc + 1) * 128 + row) * D_ + cc * 8);
            }
            cpasync_commit();
        }

        // two 64-col sub-groups; same c_s registers
#pragma unroll
        for (int hj = 0; hj < 2; hj++) {
            wmma::fragment<wmma::accumulator, 16, 16, 16, float> c_s[2][2];
#pragma unroll
            for (int i = 0; i < 2; i++)
#pragma unroll
                for (int j = 0; j < 2; j++) wmma::fill_fragment(c_s[i][j], 0.f);
#pragma unroll
            for (int ks = 0; ks < 4; ks++) {
                wmma::fragment<wmma::matrix_b, 16, 16, 16, __half, wmma::col_major> bb[2];
#pragma unroll
                for (int j = 0; j < 2; j++)
                    wmma::load_matrix_sync(bb[j],
                        &Kc[(64 * wn + 32 * hj + 16 * j) * 72 + ks * 16], 72);
#pragma unroll
                for (int i = 0; i < 2; i++)
#pragma unroll
                    for (int j = 0; j < 2; j++)
                        wmma::mma_sync(c_s[i][j], Qf[ks][i], bb[j], c_s[i][j]);
            }

#pragma unroll
            for (int i = 0; i < 2; i++) {
                float s0 = 0.f, s1 = 0.f;
#pragma unroll
                for (int j = 0; j < 2; j++) {
#pragma unroll
                    for (int e = 0; e < 8; e++)
                        c_s[i][j].x[e] = __expf(c_s[i][j].x[e]);
                    s0 += c_s[i][j].x[0] + c_s[i][j].x[1]
                        + c_s[i][j].x[4] + c_s[i][j].x[5];
                    s1 += c_s[i][j].x[2] + c_s[i][j].x[3]
                        + c_s[i][j].x[6] + c_s[i][j].x[7];
                }
                s0 += __shfl_xor_sync(0xffffffffu, s0, 1);
                s0 += __shfl_xor_sync(0xffffffffu, s0, 2);
                s1 += __shfl_xor_sync(0xffffffffu, s1, 1);
                s1 += __shfl_xor_sync(0xffffffffu, s1, 2);
                rs0[i] += s0;
                rs1[i] += s1;
            }
        }
    }

    // ---- combine across wn warps via smem (Sst reused: part[2][128]) ----
    float* part = Sst;
    if ((lane & 3) == 0) {
#pragma unroll
        for (int i = 0; i < 2; i++) {
            part[wn * 128 + 32 * wm + 16 * i + frow]     = rs0[i];
            part[wn * 128 + 32 * wm + 16 * i + frow + 8] = rs1[i];
        }
    }
    __syncthreads();

    float invr[8];
#pragma unroll
    for (int it = 0; it < 8; it++) {
        int row = 32 * wm + 4 * it + srow;
        invr[it] = 1.0f / (part[row] + part[128 + row]);
    }

    wmma::fragment<wmma::accumulator, 16, 16, 16, float> c_o[2][2];
#pragma unroll
    for (int i = 0; i < 2; i++)
#pragma unroll
        for (int j = 0; j < 2; j++) wmma::fill_fragment(c_o[i][j], 0.f);

    __syncthreads();   // part consumed; buffers free for pass 2

    // ================= PASS 2: normalized P + PV, k-chunk 64 ==========
#pragma unroll
    for (int it = 0; it < 2; it++) {
        int row = crow + 32 * it;
        cpasync16(smb + KB_BOFF + row * 144 + cc * 16,
                  Kb + (size_t)row * D_ + cc * 8);
        cpasync16(smb + VB_BOFF + row * 144 + cc * 16,
                  Vb + (size_t)row * D_ + cc * 8);
    }
    cpasync_commit();

    for (int kc = 0; kc < 32; kc++) {
        const int cur = kc & 1;
        __half* Kc = (__half*)(smc + KB_BOFF + cur * KV_BSTRIDE);
        __half* Vc = (__half*)(smc + VB_BOFF + cur * KV_BSTRIDE);

        cpasync_wait0();
        __syncthreads();

        if (kc + 1 < 32) {
            const int nxt = 1 - cur;
#pragma unroll
            for (int it = 0; it < 2; it++) {
                int row = crow + 32 * it;
                cpasync16(smb + KB_BOFF + nxt * KV_BSTRIDE + row * 144 + cc * 16,
                          Kb + (size_t)((kc + 1) * 64 + row) * D_ + cc * 8);
                cpasync16(smb + VB_BOFF + nxt * KV_BSTRIDE + row * 144 + cc * 16,
                          Vb + (size_t)((kc + 1) * 64 + row) * D_ + cc * 8);
            }
            cpasync_commit();
        }

        wmma::fragment<wmma::accumulator, 16, 16, 16, float> c_s[2][2];
#pragma unroll
        for (int i = 0; i < 2; i++)
#pragma unroll
            for (int j = 0; j < 2; j++) wmma::fill_fragment(c_s[i][j], 0.f);
#pragma unroll
        for (int ks = 0; ks < 4; ks++) {
            wmma::fragment<wmma::matrix_b, 16, 16, 16, __half, wmma::col_major> bb[2];
#pragma unroll
            for (int j = 0; j < 2; j++)
                wmma::load_matrix_sync(bb[j], &Kc[(32 * wn + 16 * j) * 72 + ks * 16], 72);
#pragma unroll
            for (int i = 0; i < 2; i++)
#pragma unroll
                for (int j = 0; j < 2; j++)
                    wmma::mma_sync(c_s[i][j], Qf[ks][i], bb[j], c_s[i][j]);
        }

        // exp in frags, store to OWN 32x32 region of Sst
#pragma unroll
        for (int i = 0; i < 2; i++)
#pragma unroll
            for (int j = 0; j < 2; j++) {
#pragma unroll
                for (int e = 0; e < 8; e++)
                    c_s[i][j].x[e] = __expf(c_s[i][j].x[e]);
                wmma::store_matrix_sync(&Sst[(32 * wm + 16 * i) * 72 + 32 * wn + 16 * j],
                                        c_s[i][j], 72, wmma::mem_row_major);
            }
        __syncwarp();

        // own-region staging: normalize -> PsH only (no gmem yet)
#pragma unroll
        for (int it = 0; it < 8; it++) {
            const int row = 32 * wm + 4 * it + srow;
            const int col = 32 * wn + sc4 * 4;
            float4 v = *(float4*)&Sst[row * 72 + col];
            const float iv = invr[it];
            half2 h0 = __floats2half2_rn(v.x * iv, v.y * iv);
            half2 h1 = __floats2half2_rn(v.z * iv, v.w * iv);
            uint2 pk; pk.x = *(uint32_t*)&h0; pk.y = *(uint32_t*)&h1;
            *(uint2*)&PsH[row * 72 + col] = pk;
        }
        __syncthreads();   // PsH complete across warps

        // O += PsH(128x64) @ Vc(64x64)
#pragma unroll
        for (int ks = 0; ks < 4; ks++) {
            wmma::fragment<wmma::matrix_a, 16, 16, 16, __half, wmma::row_major> a2[2];
            wmma::fragment<wmma::matrix_b, 16, 16, 16, __half, wmma::row_major> b2[2];
#pragma unroll
            for (int i = 0; i < 2; i++)
                wmma::load_matrix_sync(a2[i], &PsH[(32 * wm + 16 * i) * 72 + ks * 16], 72);
#pragma unroll
            for (int j = 0; j < 2; j++)
                wmma::load_matrix_sync(b2[j], &Vc[(ks * 16) * 72 + 32 * wn + 16 * j], 72);
#pragma unroll
            for (int i = 0; i < 2; i++)
#pragma unroll
                for (int j = 0; j < 2; j++)
                    wmma::mma_sync(c_o[i][j], a2[i], b2[j], c_o[i][j]);
        }

        // fp32 P write AFTER PV (overlaps tensor drain); Sst still valid
#pragma unroll
        for (int it = 0; it < 8; it++) {
            const int row = 32 * wm + 4 * it + srow;
            const int col = 32 * wn + sc4 * 4;
            float4 v = *(float4*)&Sst[row * 72 + col];
            const float iv = invr[it];
            v.x *= iv; v.y *= iv; v.z *= iv; v.w *= iv;
            *(float4*)(Pb + (size_t)(q0 + row) * S_ + kc * 64 + col) = v;
        }
    }

    // ---- O frags (normalized) -> stage -> AO (half) ----
    __syncthreads();
#pragma unroll
    for (int i = 0; i < 2; i++)
#pragma unroll
        for (int j = 0; j < 2; j++)
            wmma::store_matrix_sync(&Sst[(32 * wm + 16 * i) * 72 + 32 * wn + 16 * j],
                                    c_o[i][j], 72, wmma::mem_row_major);
    __syncthreads();

#pragma unroll
    for (int it = 0; it < 8; it++) {
        int row = prow + 16 * it;
        float4 v = *(float4*)&Sst[row * 72 + pc4 * 4];
        half2 h0 = __floats2half2_rn(v.x, v.y);
        half2 h1 = __floats2half2_rn(v.z, v.w);
        uint2 pk; pk.x = *(uint32_t*)&h0; pk.y = *(uint32_t*)&h1;
        *(uint2*)(AO + ((size_t)b * S_ + q0 + row) * D_ + h * DK_ + pc4 * 4) = pk;
    }
}

// ---------------------------------------------------------------------------
extern "C" void kernel_launch(void* const* d_in, const int* in_sizes, int n_in,
                              void* d_out, int out_size)
{
    const float* query = (const float*)d_in[0];
    const float* key_  = (const float*)d_in[1];
    const float* value = (const float*)d_in[2];
    const float* Wq = (const float*)d_in[3];
    const float* bq = (const float*)d_in[4];
    const float* Wk = (const float*)d_in[5];
    const float* bk = (const float*)d_in[6];
    const float* Wv = (const float*)d_in[7];
    const float* bv = (const float*)d_in[8];
    const float* Wo = (const float*)d_in[9];
    const float* bo = (const float*)d_in[10];

    float* out  = (float*)d_out;
    float* attn = out + (size_t)B_ * S_ * D_;

    __half *Xq, *Xk, *Xv, *Wh, *Qh, *Kh, *Vh, *AOh;
    cudaGetSymbolAddress((void**)&Xq,  g_Xq);
    cudaGetSymbolAddress((void**)&Xk,  g_Xk);
    cudaGetSymbolAddress((void**)&Xv,  g_Xv);
    cudaGetSymbolAddress((void**)&Wh,  g_Wh);
    cudaGetSymbolAddress((void**)&Qh,  g_Qh);
    cudaGetSymbolAddress((void**)&Kh,  g_Kh);
    cudaGetSymbolAddress((void**)&Vh,  g_Vh);
    cudaGetSymbolAddress((void**)&AOh, g_AOh);

    cudaFuncSetAttribute(fused_attn16,
                         cudaFuncAttributeMaxDynamicSharedMemorySize, FA_SMEM_BYTES);
    cudaFuncSetAttribute(qkv16,
                         cudaFuncAttributeMaxDynamicSharedMemorySize, G16_SMEM_BYTES);
    cudaFuncSetAttribute(out16,
                         cudaFuncAttributeMaxDynamicSharedMemorySize, G16_SMEM_BYTES);

    tohalf_all<<<dim3(1024, 7), 256>>>(query, key_, value, Wq, Wk, Wv, Wo,
                                       Xq, Xk, Xv, Wh);

    qkv16<<<dim3(8, 128, 3), 256, G16_SMEM_BYTES>>>(
        Xq, Xk, Xv,
        Wh + 0 * (size_t)D_ * D_, bq,
        Wh + 1 * (size_t)D_ * D_, bk,
        Wh + 2 * (size_t)D_ * D_, bv,
        Qh, Kh, Vh);

    fused_attn16<<<dim3(16, 64), 256, FA_SMEM_BYTES>>>(Qh, Kh, Vh, attn, AOh);

    out16<<<dim3(8, 128), 256, G16_SMEM_BYTES>>>(AOh, Wh + 3 * (size_t)D_ * D_, bo, out);
}

// round 17
// speedup vs baseline: 1.0605x; 1.0605x over previous
#include <cuda_runtime.h>
#include <mma.h>
#include <cuda_fp16.h>
#include <cstdint>

using namespace nvcuda;

#define B_  4
#define S_  2048
#define D_  1024
#define H_  16
#define DK_ 64

// Scratch (__device__ globals; no allocs allowed).
__device__ __half g_Xq[(size_t)B_*S_*D_];
__device__ __half g_Xk[(size_t)B_*S_*D_];
__device__ __half g_Xv[(size_t)B_*S_*D_];
__device__ __half g_Wh[4][(size_t)D_*D_];
__device__ __half g_Qh[(size_t)B_*S_*D_];   // Qproj * 0.125
__device__ __half g_Kh[(size_t)B_*S_*D_];
__device__ __half g_Vh[(size_t)B_*S_*D_];
__device__ __half g_AOh[(size_t)B_*S_*D_];

__device__ __forceinline__ void cpasync16(uint32_t saddr, const void* g) {
    asm volatile("cp.async.cg.shared.global [%0], [%1], 16;" :: "r"(saddr), "l"(g));
}
__device__ __forceinline__ void cpasync_commit() {
    asm volatile("cp.async.commit_group;");
}
__device__ __forceinline__ void cpasync_wait0() {
    asm volatile("cp.async.wait_group 0;");
}

// ---------------------------------------------------------------------------
// fp32 -> fp16 conversion, all 7 tensors in one launch.
// ---------------------------------------------------------------------------
__global__ __launch_bounds__(256) void tohalf_all(
    const float* __restrict__ q,  const float* __restrict__ k,
    const float* __restrict__ v,
    const float* __restrict__ wq, const float* __restrict__ wk,
    const float* __restrict__ wv, const float* __restrict__ wo,
    __half* __restrict__ xq, __half* __restrict__ xk, __half* __restrict__ xv,
    __half* __restrict__ wh)
{
    const int z = blockIdx.y;
    const float* in; __half* o; int n4;
    const int NB = (int)((size_t)B_ * S_ * D_ / 4);
    const int NW = D_ * D_ / 4;
    if (z == 0)      { in = q;  o = xq; n4 = NB; }
    else if (z == 1) { in = k;  o = xk; n4 = NB; }
    else if (z == 2) { in = v;  o = xv; n4 = NB; }
    else if (z == 3) { in = wq; o = wh + 0 * (size_t)D_ * D_; n4 = NW; }
    else if (z == 4) { in = wk; o = wh + 1 * (size_t)D_ * D_; n4 = NW; }
    else if (z == 5) { in = wv; o = wh + 2 * (size_t)D_ * D_; n4 = NW; }
    else             { in = wo; o = wh + 3 * (size_t)D_ * D_; n4 = NW; }

    int i = blockIdx.x * 256 + threadIdx.x;
    int stride = gridDim.x * 256;
    for (; i < n4; i += stride) {
        float4 vv = ((const float4*)in)[i];
        half2 h0 = __floats2half2_rn(vv.x, vv.y);
        half2 h1 = __floats2half2_rn(vv.z, vv.w);
        uint2 pk; pk.x = *(uint32_t*)&h0; pk.y = *(uint32_t*)&h1;
        ((uint2*)o)[i] = pk;
    }
}

// ---------------------------------------------------------------------------
// fp16 NT GEMM, BM=64 / BN=128 / BK=64, 4 CTAs/SM.
// Cs epilogue buffer ALIASES the A/B buffers (dead after mainloop; guarded
// by a post-loop __syncthreads). Smem/CTA = 55296 B.
// mode 0: fp32 out. 1: half out. 2: half out * 0.125.
// ---------------------------------------------------------------------------
#define GA_BUF 9216
#define GB_BUF 18432
#define GB_BASE 18432
#define G16_SMEM_BYTES 55296

__device__ __forceinline__ void gemm16_body(
    const __half* __restrict__ A, const __half* __restrict__ W,
    const float* __restrict__ bias, float* __restrict__ Cf,
    __half* __restrict__ Ch, int mode, char* smc)
{
    const int tid = threadIdx.x;
    const int w = tid >> 5, lane = tid & 31;
    const int wm = w >> 2, wn = w & 3;
    const size_t m0 = (size_t)blockIdx.y * 64;
    const size_t n0 = (size_t)blockIdx.x * 128;
    const uint32_t smb = (uint32_t)__cvta_generic_to_shared(smc);
    const int crow = tid >> 3, cc = tid & 7;

    wmma::fragment<wmma::accumulator, 16, 16, 16, float> c[2][2];
#pragma unroll
    for (int i = 0; i < 2; i++)
#pragma unroll
        for (int j = 0; j < 2; j++) wmma::fill_fragment(c[i][j], 0.f);

#pragma unroll
    for (int it = 0; it < 2; it++) {
        int row = crow + 32 * it;
        cpasync16(smb + row * 144 + cc * 16,
                  A + (m0 + row) * 1024 + cc * 8);
    }
#pragma unroll
    for (int it = 0; it < 4; it++) {
        int row = crow + 32 * it;
        cpasync16(smb + GB_BASE + row * 144 + cc * 16,
                  W + (n0 + row) * 1024 + cc * 8);
    }
    cpasync_commit();

    for (int kb = 0; kb < 16; kb++) {
        const int cur = kb & 1;
        cpasync_wait0();
        __syncthreads();

        if (kb < 15) {
            const int nxt = 1 - cur;
            const int k0 = (kb + 1) * 64;
#pragma unroll
            for (int it = 0; it < 2; it++) {
                int row = crow + 32 * it;
                cpasync16(smb + nxt * GA_BUF + row * 144 + cc * 16,
                          A + (m0 + row) * 1024 + k0 + cc * 8);
            }
#pragma unroll
            for (int it = 0; it < 4; it++) {
                int row = crow + 32 * it;
                cpasync16(smb + GB_BASE + nxt * GB_BUF + row * 144 + cc * 16,
                          W + (n0 + row) * 1024 + k0 + cc * 8);
            }
            cpasync_commit();
        }

        const __half* ah = (const __half*)(smc + cur * GA_BUF);
        const __half* bh = (const __half*)(smc + GB_BASE + cur * GB_BUF);
#pragma unroll
        for (int ks = 0; ks < 4; ks++) {
            wmma::fragment<wmma::matrix_a, 16, 16, 16, __half, wmma::row_major> a[2];
            wmma::fragment<wmma::matrix_b, 16, 16, 16, __half, wmma::col_major> b[2];
#pragma unroll
            for (int i = 0; i < 2; i++)
                wmma::load_matrix_sync(a[i], &ah[(32 * wm + 16 * i) * 72 + ks * 16], 72);
#pragma unroll
            for (int j = 0; j < 2; j++)
                wmma::load_matrix_sync(b[j], &bh[(32 * wn + 16 * j) * 72 + ks * 16], 72);
#pragma unroll
            for (int i = 0; i < 2; i++)
#pragma unroll
                for (int j = 0; j < 2; j++)
                    wmma::mma_sync(c[i][j], a[i], b[j], c[i][j]);
        }
    }

    __syncthreads();   // all warps done with A/B buffers; safe to alias Cs

    float* buf = (float*)smc + w * 320;   // Cs aliases buffer region
#pragma unroll
    for (int i = 0; i < 2; i++) {
#pragma unroll
        for (int j = 0; j < 2; j++) {
            wmma::store_matrix_sync(buf, c[i][j], 20, wmma::mem_row_major);
            __syncwarp();
            const int rr = lane >> 1, ch = (lane & 1) * 8;
            const size_t gr = m0 + 32 * wm + 16 * i + rr;
            const size_t gc = n0 + 32 * wn + 16 * j + ch;
            float4 v0 = *(float4*)&buf[rr * 20 + ch];
            float4 v1 = *(float4*)&buf[rr * 20 + ch + 4];
            v0.x += bias[gc + 0]; v0.y += bias[gc + 1];
            v0.z += bias[gc + 2]; v0.w += bias[gc + 3];
            v1.x += bias[gc + 4]; v1.y += bias[gc + 5];
            v1.z += bias[gc + 6]; v1.w += bias[gc + 7];
            if (mode == 0) {
                *(float4*)(Cf + gr * 1024 + gc)     = v0;
                *(float4*)(Cf + gr * 1024 + gc + 4) = v1;
            } else {
                if (mode == 2) {
                    v0.x *= 0.125f; v0.y *= 0.125f; v0.z *= 0.125f; v0.w *= 0.125f;
                    v1.x *= 0.125f; v1.y *= 0.125f; v1.z *= 0.125f; v1.w *= 0.125f;
                }
                half2 h0 = __floats2half2_rn(v0.x, v0.y);
                half2 h1 = __floats2half2_rn(v0.z, v0.w);
                half2 h2 = __floats2half2_rn(v1.x, v1.y);
                half2 h3 = __floats2half2_rn(v1.z, v1.w);
                uint4 pk;
                pk.x = *(uint32_t*)&h0; pk.y = *(uint32_t*)&h1;
                pk.z = *(uint32_t*)&h2; pk.w = *(uint32_t*)&h3;
                *(uint4*)(Ch + gr * 1024 + gc) = pk;
            }
            __syncwarp();
        }
    }
}

__global__ __launch_bounds__(256, 4) void qkv16(
    const __half* __restrict__ xq, const __half* __restrict__ xk,
    const __half* __restrict__ xv,
    const __half* __restrict__ wq, const float* __restrict__ bq,
    const __half* __restrict__ wk, const float* __restrict__ bk,
    const __half* __restrict__ wv, const float* __restrict__ bv,
    __half* __restrict__ Qo, __half* __restrict__ Ko, __half* __restrict__ Vo)
{
    extern __shared__ char smc[];
    const __half *A, *W; const float* bi; __half* C; int mode;
    if (blockIdx.z == 0)      { A = xq; W = wq; bi = bq; C = Qo; mode = 2; }
    else if (blockIdx.z == 1) { A = xk; W = wk; bi = bk; C = Ko; mode = 1; }
    else                      { A = xv; W = wv; bi = bv; C = Vo; mode = 1; }
    gemm16_body(A, W, bi, nullptr, C, mode, smc);
}

__global__ __launch_bounds__(256, 4) void out16(
    const __half* __restrict__ A, const __half* __restrict__ W,
    const float* __restrict__ bi, float* __restrict__ C)
{
    extern __shared__ char smc[];
    gemm16_body(A, W, bi, C, nullptr, 0, smc);
}

// ---------------------------------------------------------------------------
// Fused attention, TWO-PASS (exact R14 version, 676.7us proven).
// Pass 1: in-fragment rowsums (1 barrier/chunk).
// Pass 2: per-warp own-region staging (normalize -> fp32 P + half PsH),
//         then PV; 2 barriers/chunk.
// Smem: Sst f32 128*72 @0, PsH half @36864, KB dbl @55296, VB dbl @73728.
// ---------------------------------------------------------------------------
#define FA_SMEM_BYTES 92160
#define KB_BOFF 55296
#define VB_BOFF 73728
#define KV_BSTRIDE 9216

__global__ __launch_bounds__(256, 2) void fused_attn16(
    const __half* __restrict__ Q, const __half* __restrict__ K,
    const __half* __restrict__ V, float* __restrict__ P,
    __half* __restrict__ AO)
{
    extern __shared__ char smc[];
    float*  Sst = (float*)smc;
    __half* PsH = (__half*)(smc + 36864);
    const uint32_t smb = (uint32_t)__cvta_generic_to_shared(smc);

    const int tid = threadIdx.x, w = tid >> 5, lane = tid & 31;
    const int wm = w >> 1, wn = w & 1;          // 4x2 warp grid, 32x32 tiles
    const int bh = blockIdx.y, b = bh >> 4, h = bh & 15;
    const int q0 = blockIdx.x * 128;
    const int prow = tid >> 4, pc4 = tid & 15;  // block-wide pass mapping
    const int crow = tid >> 3, cc = tid & 7;    // K/V copy mapping
    const int frow = lane >> 2;                 // fragment row base
    const int srow = lane >> 3, sc4 = lane & 7; // own-region staging mapping

    const __half* Qb = Q + (size_t)b * S_ * D_ + h * DK_;
    const __half* Kb = K + (size_t)b * S_ * D_ + h * DK_;
    const __half* Vb = V + (size_t)b * S_ * D_ + h * DK_;
    float* Pb = P + (size_t)bh * S_ * S_;

    // ---- Stage Q tile into PsH, preload fragments ----
#pragma unroll
    for (int it = 0; it < 4; it++) {
        int idx = tid + 256 * it;
        int row = idx >> 3, c = idx & 7;
        *(uint4*)&PsH[row * 72 + c * 8] =
            *(const uint4*)(Qb + (size_t)(q0 + row) * D_ + c * 8);
    }
    __syncthreads();
    wmma::fragment<wmma::matrix_a, 16, 16, 16, __half, wmma::row_major> Qf[4][2];
#pragma unroll
    for (int ks = 0; ks < 4; ks++)
#pragma unroll
        for (int i = 0; i < 2; i++)
            wmma::load_matrix_sync(Qf[ks][i], &PsH[(32 * wm + 16 * i) * 72 + ks * 16], 72);
    __syncthreads();

    float rs0[2] = {0.f, 0.f};
    float rs1[2] = {0.f, 0.f};

    // ================= PASS 1: rowsums =================
#pragma unroll
    for (int it = 0; it < 2; it++) {
        int row = crow + 32 * it;
        cpasync16(smb + KB_BOFF + row * 144 + cc * 16,
                  Kb + (size_t)row * D_ + cc * 8);
    }
    cpasync_commit();

    for (int kc = 0; kc < 32; kc++) {
        const int cur = kc & 1;
        __half* Kc = (__half*)(smc + KB_BOFF + cur * KV_BSTRIDE);

        cpasync_wait0();
        __syncthreads();

        if (kc + 1 < 32) {
            const int nxt = 1 - cur;
#pragma unroll
            for (int it = 0; it < 2; it++) {
                int row = crow + 32 * it;
                cpasync16(smb + KB_BOFF + nxt * KV_BSTRIDE + row * 144 + cc * 16,
                          Kb + (size_t)((kc + 1) * 64 + row) * D_ + cc * 8);
            }
            cpasync_commit();
        }

        wmma::fragment<wmma::accumulator, 16, 16, 16, float> c_s[2][2];
#pragma unroll
        for (int i = 0; i < 2; i++)
#pragma unroll
            for (int j = 0; j < 2; j++) wmma::fill_fragment(c_s[i][j], 0.f);
#pragma unroll
        for (int ks = 0; ks < 4; ks++) {
            wmma::fragment<wmma::matrix_b, 16, 16, 16, __half, wmma::col_major> bb[2];
#pragma unroll
            for (int j = 0; j < 2; j++)
                wmma::load_matrix_sync(bb[j], &Kc[(32 * wn + 16 * j) * 72 + ks * 16], 72);
#pragma unroll
            for (int i = 0; i < 2; i++)
#pragma unroll
                for (int j = 0; j < 2; j++)
                    wmma::mma_sync(c_s[i][j], Qf[ks][i], bb[j], c_s[i][j]);
        }

#pragma unroll
        for (int i = 0; i < 2; i++) {
            float s0 = 0.f, s1 = 0.f;
#pragma unroll
            for (int j = 0; j < 2; j++) {
#pragma unroll
                for (int e = 0; e < 8; e++)
                    c_s[i][j].x[e] = __expf(c_s[i][j].x[e]);
                s0 += c_s[i][j].x[0] + c_s[i][j].x[1]
                    + c_s[i][j].x[4] + c_s[i][j].x[5];
                s1 += c_s[i][j].x[2] + c_s[i][j].x[3]
                    + c_s[i][j].x[6] + c_s[i][j].x[7];
            }
            s0 += __shfl_xor_sync(0xffffffffu, s0, 1);
            s0 += __shfl_xor_sync(0xffffffffu, s0, 2);
            s1 += __shfl_xor_sync(0xffffffffu, s1, 1);
            s1 += __shfl_xor_sync(0xffffffffu, s1, 2);
            rs0[i] += s0;
            rs1[i] += s1;
        }
    }

    // ---- combine across wn warps via smem (Sst reused: part[2][128]) ----
    float* part = Sst;
    if ((lane & 3) == 0) {
#pragma unroll
        for (int i = 0; i < 2; i++) {
            part[wn * 128 + 32 * wm + 16 * i + frow]     = rs0[i];
            part[wn * 128 + 32 * wm + 16 * i + frow + 8] = rs1[i];
        }
    }
    __syncthreads();

    float invr[8];
#pragma unroll
    for (int it = 0; it < 8; it++) {
        int row = 32 * wm + 4 * it + srow;
        invr[it] = 1.0f / (part[row] + part[128 + row]);
    }

    wmma::fragment<wmma::accumulator, 16, 16, 16, float> c_o[2][2];
#pragma unroll
    for (int i = 0; i < 2; i++)
#pragma unroll
        for (int j = 0; j < 2; j++) wmma::fill_fragment(c_o[i][j], 0.f);

    __syncthreads();   // part consumed before Sst reuse

    // ================= PASS 2: normalized P + PV =================
#pragma unroll
    for (int it = 0; it < 2; it++) {
        int row = crow + 32 * it;
        cpasync16(smb + KB_BOFF + row * 144 + cc * 16,
                  Kb + (size_t)row * D_ + cc * 8);
        cpasync16(smb + VB_BOFF + row * 144 + cc * 16,
                  Vb + (size_t)row * D_ + cc * 8);
    }
    cpasync_commit();

    for (int kc = 0; kc < 32; kc++) {
        const int cur = kc & 1;
        __half* Kc = (__half*)(smc + KB_BOFF + cur * KV_BSTRIDE);
        __half* Vc = (__half*)(smc + VB_BOFF + cur * KV_BSTRIDE);

        cpasync_wait0();
        __syncthreads();

        if (kc + 1 < 32) {
            const int nxt = 1 - cur;
#pragma unroll
            for (int it = 0; it < 2; it++) {
                int row = crow + 32 * it;
                cpasync16(smb + KB_BOFF + nxt * KV_BSTRIDE + row * 144 + cc * 16,
                          Kb + (size_t)((kc + 1) * 64 + row) * D_ + cc * 8);
                cpasync16(smb + VB_BOFF + nxt * KV_BSTRIDE + row * 144 + cc * 16,
                          Vb + (size_t)((kc + 1) * 64 + row) * D_ + cc * 8);
            }
            cpasync_commit();
        }

        wmma::fragment<wmma::accumulator, 16, 16, 16, float> c_s[2][2];
#pragma unroll
        for (int i = 0; i < 2; i++)
#pragma unroll
            for (int j = 0; j < 2; j++) wmma::fill_fragment(c_s[i][j], 0.f);
#pragma unroll
        for (int ks = 0; ks < 4; ks++) {
            wmma::fragment<wmma::matrix_b, 16, 16, 16, __half, wmma::col_major> bb[2];
#pragma unroll
            for (int j = 0; j < 2; j++)
                wmma::load_matrix_sync(bb[j], &Kc[(32 * wn + 16 * j) * 72 + ks * 16], 72);
#pragma unroll
            for (int i = 0; i < 2; i++)
#pragma unroll
                for (int j = 0; j < 2; j++)
                    wmma::mma_sync(c_s[i][j], Qf[ks][i], bb[j], c_s[i][j]);
        }

        // exp in frags, store to OWN 32x32 region of Sst
#pragma unroll
        for (int i = 0; i < 2; i++)
#pragma unroll
            for (int j = 0; j < 2; j++) {
#pragma unroll
                for (int e = 0; e < 8; e++)
                    c_s[i][j].x[e] = __expf(c_s[i][j].x[e]);
                wmma::store_matrix_sync(&Sst[(32 * wm + 16 * i) * 72 + 32 * wn + 16 * j],
                                        c_s[i][j], 72, wmma::mem_row_major);
            }
        __syncwarp();

        // own-region staging: normalize, write fp32 P, half PsH
#pragma unroll
        for (int it = 0; it < 8; it++) {
            const int row = 32 * wm + 4 * it + srow;
            const int col = 32 * wn + sc4 * 4;
            float4 v = *(float4*)&Sst[row * 72 + col];
            const float iv = invr[it];
            v.x *= iv; v.y *= iv; v.z *= iv; v.w *= iv;
            *(float4*)(Pb + (size_t)(q0 + row) * S_ + kc * 64 + col) = v;
            half2 h0 = __floats2half2_rn(v.x, v.y);
            half2 h1 = __floats2half2_rn(v.z, v.w);
            uint2 pk; pk.x = *(uint32_t*)&h0; pk.y = *(uint32_t*)&h1;
            *(uint2*)&PsH[row * 72 + col] = pk;
        }
        __syncthreads();   // PsH complete across warps

        // O += PsH(128x64) @ Vc(64x64)
#pragma unroll
        for (int ks = 0; ks < 4; ks++) {
            wmma::fragment<wmma::matrix_a, 16, 16, 16, __half, wmma::row_major> a2[2];
            wmma::fragment<wmma::matrix_b, 16, 16, 16, __half, wmma::row_major> b2[2];
#pragma unroll
            for (int i = 0; i < 2; i++)
                wmma::load_matrix_sync(a2[i], &PsH[(32 * wm + 16 * i) * 72 + ks * 16], 72);
#pragma unroll
            for (int j = 0; j < 2; j++)
                wmma::load_matrix_sync(b2[j], &Vc[(ks * 16) * 72 + 32 * wn + 16 * j], 72);
#pragma unroll
            for (int i = 0; i < 2; i++)
#pragma unroll
                for (int j = 0; j < 2; j++)
                    wmma::mma_sync(c_o[i][j], a2[i], b2[j], c_o[i][j]);
        }
    }

    // ---- O frags (normalized P => normalized O) -> stage -> AO (half) ----
    __syncthreads();
#pragma unroll
    for (int i = 0; i < 2; i++)
#pragma unroll
        for (int j = 0; j < 2; j++)
            wmma::store_matrix_sync(&Sst[(32 * wm + 16 * i) * 72 + 32 * wn + 16 * j],
                                    c_o[i][j], 72, wmma::mem_row_major);
    __syncthreads();

#pragma unroll
    for (int it = 0; it < 8; it++) {
        int row = prow + 16 * it;
        float4 v = *(float4*)&Sst[row * 72 + pc4 * 4];
        half2 h0 = __floats2half2_rn(v.x, v.y);
        half2 h1 = __floats2half2_rn(v.z, v.w);
        uint2 pk; pk.x = *(uint32_t*)&h0; pk.y = *(uint32_t*)&h1;
        *(uint2*)(AO + ((size_t)b * S_ + q0 + row) * D_ + h * DK_ + pc4 * 4) = pk;
    }
}

// ---------------------------------------------------------------------------
extern "C" void kernel_launch(void* const* d_in, const int* in_sizes, int n_in,
                              void* d_out, int out_size)
{
    const float* query = (const float*)d_in[0];
    const float* key_  = (const float*)d_in[1];
    const float* value = (const float*)d_in[2];
    const float* Wq = (const float*)d_in[3];
    const float* bq = (const float*)d_in[4];
    const float* Wk = (const float*)d_in[5];
    const float* bk = (const float*)d_in[6];
    const float* Wv = (const float*)d_in[7];
    const float* bv = (const float*)d_in[8];
    const float* Wo = (const float*)d_in[9];
    const float* bo = (const float*)d_in[10];

    float* out  = (float*)d_out;
    float* attn = out + (size_t)B_ * S_ * D_;

    __half *Xq, *Xk, *Xv, *Wh, *Qh, *Kh, *Vh, *AOh;
    cudaGetSymbolAddress((void**)&Xq,  g_Xq);
    cudaGetSymbolAddress((void**)&Xk,  g_Xk);
    cudaGetSymbolAddress((void**)&Xv,  g_Xv);
    cudaGetSymbolAddress((void**)&Wh,  g_Wh);
    cudaGetSymbolAddress((void**)&Qh,  g_Qh);
    cudaGetSymbolAddress((void**)&Kh,  g_Kh);
    cudaGetSymbolAddress((void**)&Vh,  g_Vh);
    cudaGetSymbolAddress((void**)&AOh, g_AOh);

    cudaFuncSetAttribute(fused_attn16,
                         cudaFuncAttributeMaxDynamicSharedMemorySize, FA_SMEM_BYTES);
    cudaFuncSetAttribute(qkv16,
                         cudaFuncAttributeMaxDynamicSharedMemorySize, G16_SMEM_BYTES);
    cudaFuncSetAttribute(out16,
                         cudaFuncAttributeMaxDynamicSharedMemorySize, G16_SMEM_BYTES);

    tohalf_all<<<dim3(1024, 7), 256>>>(query, key_, value, Wq, Wk, Wv, Wo,
                                       Xq, Xk, Xv, Wh);

    qkv16<<<dim3(8, 128, 3), 256, G16_SMEM_BYTES>>>(
        Xq, Xk, Xv,
        Wh + 0 * (size_t)D_ * D_, bq,
        Wh + 1 * (size_t)D_ * D_, bk,
        Wh + 2 * (size_t)D_ * D_, bv,
        Qh, Kh, Vh);

    fused_attn16<<<dim3(16, 64), 256, FA_SMEM_BYTES>>>(Qh, Kh, Vh, attn, AOh);

    out16<<<dim3(8, 128), 256, G16_SMEM_BYTES>>>(AOh, Wh + 3 * (size_t)D_ * D_, bo, out);
}